// round 4
// baseline (speedup 1.0000x reference)
#include <cuda_runtime.h>
#include <math.h>

#define N_NODES 100000
#define N_EDGES 3200000
#define N_FEAT  512
#define HIDDEN  16

typedef unsigned long long ull;

// ---- scratch (device globals; no runtime allocation) ----
__device__ float d_g[(size_t)N_NODES * HIDDEN];    // dinv[n] * (x[n] @ W1)
__device__ float d_agg[(size_t)N_NODES * HIDDEN];  // scatter-add target
__device__ int   d_deg[N_NODES];
__device__ float d_dinv[N_NODES];
__device__ float d_csrc[N_NODES];                  // sum over out-edges of dinv[dst]
__device__ float d_s[HIDDEN];                      // sum_n c[n] * r[n]

// ---- PTX helpers ----
__device__ __forceinline__ ull pack2(float x, float y) {
    ull r; asm("mov.b64 %0, {%1, %2};" : "=l"(r) : "f"(x), "f"(y)); return r;
}
__device__ __forceinline__ void unpack2(ull v, float& x, float& y) {
    asm("mov.b64 {%0, %1}, %2;" : "=f"(x), "=f"(y) : "l"(v));
}
__device__ __forceinline__ void fma2(ull& acc, ull a, ull b) {
    asm("fma.rn.f32x2 %0, %1, %2, %0;" : "+l"(acc) : "l"(a), "l"(b));
}
__device__ __forceinline__ void red4(float* p, float4 v) {
    asm volatile("red.global.add.v4.f32 [%0], {%1, %2, %3, %4};"
                 :: "l"(p), "f"(v.x), "f"(v.y), "f"(v.z), "f"(v.w) : "memory");
}

// ---- K0: zero scratch ----
__global__ void zero_kernel() {
    int i = blockIdx.x * blockDim.x + threadIdx.x;
    if (i < (N_NODES * HIDDEN) / 4) {
        ((float4*)d_agg)[i] = make_float4(0.f, 0.f, 0.f, 0.f);
    }
    if (i < N_NODES) { d_deg[i] = 0; d_csrc[i] = 0.f; }
    if (i < HIDDEN)  { d_s[i] = 0.f; }
}

// ---- K1: in-degree histogram over dst (4 edges/thread) ----
__global__ void hist_kernel(const int4* __restrict__ dst4) {
    int i = blockIdx.x * blockDim.x + threadIdx.x;
    if (i < N_EDGES / 4) {
        int4 d = dst4[i];
        atomicAdd(&d_deg[d.x], 1);
        atomicAdd(&d_deg[d.y], 1);
        atomicAdd(&d_deg[d.z], 1);
        atomicAdd(&d_deg[d.w], 1);
    }
}

// ---- K2: dinv = rsqrt(deg + 1)  (self-loop included) ----
__global__ void dinv_kernel() {
    int n = blockIdx.x * blockDim.x + threadIdx.x;
    if (n < N_NODES) d_dinv[n] = rsqrtf((float)(d_deg[n] + 1));
}

// ---- K3: g[n] = dinv[n] * (x[n] @ W1), packed f32x2 FMA, W1 in SMEM ----
__global__ __launch_bounds__(256) void gemm_kernel(
    const float* __restrict__ x, const float* __restrict__ W1)
{
    __shared__ ull sW[N_FEAT * (HIDDEN / 2)];  // 512 * 8 pairs = 32 KB
    const ull* Wg = (const ull*)W1;            // W1 row-major [512,16]: (j,j+1) adjacent
    for (int i = threadIdx.x; i < N_FEAT * (HIDDEN / 2); i += 256) sW[i] = Wg[i];
    __syncthreads();

    int n = blockIdx.x * 256 + threadIdx.x;
    int nc = (n < N_NODES) ? n : 0;  // clamp; invalid threads just don't store

    const float4* xr = (const float4*)(x + (size_t)nc * N_FEAT);
    ull acc[8];
#pragma unroll
    for (int m = 0; m < 8; m++) acc[m] = 0ull;

#pragma unroll 2
    for (int k4 = 0; k4 < N_FEAT / 4; k4++) {
        float4 xv = xr[k4];
#pragma unroll
        for (int t = 0; t < 4; t++) {
            float xk = (t == 0) ? xv.x : (t == 1) ? xv.y : (t == 2) ? xv.z : xv.w;
            ull xkk = pack2(xk, xk);
            const ull* wr = &sW[(k4 * 4 + t) * 8];
#pragma unroll
            for (int m = 0; m < 8; m++) fma2(acc[m], xkk, wr[m]);
        }
    }

    if (n < N_NODES) {
        float dv = d_dinv[n];
        float4* out = (float4*)(d_g + (size_t)n * HIDDEN);
#pragma unroll
        for (int m = 0; m < 4; m++) {
            float a, b, c, d;
            unpack2(acc[2 * m], a, b);
            unpack2(acc[2 * m + 1], c, d);
            out[m] = make_float4(a * dv, b * dv, c * dv, d * dv);
        }
    }
}

// ---- K4: edge scatter: agg[dst] += g[src] (RED.128 x4); csrc[src] += dinv[dst] ----
__global__ __launch_bounds__(256) void edge_kernel(
    const int* __restrict__ src, const int* __restrict__ dst)
{
    int e = blockIdx.x * blockDim.x + threadIdx.x;
    if (e >= N_EDGES) return;
    int s = src[e];
    int d = dst[e];
    const float4* gs = (const float4*)(d_g + (size_t)s * HIDDEN);
    float4 v0 = gs[0], v1 = gs[1], v2 = gs[2], v3 = gs[3];
    float* ad = d_agg + (size_t)d * HIDDEN;
    red4(ad + 0, v0);
    red4(ad + 4, v1);
    red4(ad + 8, v2);
    red4(ad + 12, v3);
    atomicAdd(&d_csrc[s], d_dinv[d]);
}

// ---- K5: r = relu(dinv*(agg+g) + b1); s += c*r with block reduction ----
__global__ __launch_bounds__(256) void finalize_kernel(const float* __restrict__ b1) {
    int n = blockIdx.x * blockDim.x + threadIdx.x;
    float cr[HIDDEN];
#pragma unroll
    for (int j = 0; j < HIDDEN; j++) cr[j] = 0.f;

    if (n < N_NODES) {
        float dv = d_dinv[n];
        float c = dv * (dv + d_csrc[n]);
        const float4* ag = (const float4*)(d_agg + (size_t)n * HIDDEN);
        const float4* gg = (const float4*)(d_g + (size_t)n * HIDDEN);
        const float4* bb4 = (const float4*)b1;
#pragma unroll
        for (int m = 0; m < 4; m++) {
            float4 a = ag[m], g = gg[m], bb = bb4[m];
            cr[4 * m + 0] = c * fmaxf(fmaf(dv, a.x + g.x, bb.x), 0.f);
            cr[4 * m + 1] = c * fmaxf(fmaf(dv, a.y + g.y, bb.y), 0.f);
            cr[4 * m + 2] = c * fmaxf(fmaf(dv, a.z + g.z, bb.z), 0.f);
            cr[4 * m + 3] = c * fmaxf(fmaf(dv, a.w + g.w, bb.w), 0.f);
        }
    }

    // warp tree-reduce each of the 16 components
#pragma unroll
    for (int j = 0; j < HIDDEN; j++) {
        float v = cr[j];
#pragma unroll
        for (int off = 16; off > 0; off >>= 1)
            v += __shfl_down_sync(0xffffffffu, v, off);
        cr[j] = v;
    }

    __shared__ float red[8][HIDDEN];
    int lane = threadIdx.x & 31;
    int w = threadIdx.x >> 5;
    if (lane == 0) {
#pragma unroll
        for (int j = 0; j < HIDDEN; j++) red[w][j] = cr[j];
    }
    __syncthreads();
    if (threadIdx.x < HIDDEN) {
        float t = 0.f;
#pragma unroll
        for (int ww = 0; ww < 8; ww++) t += red[ww][threadIdx.x];
        atomicAdd(&d_s[threadIdx.x], t);
    }
}

// ---- K6: pooled = s@W2/N + b2 ; softmax ; write 16 floats ----
__global__ void out_kernel(const float* __restrict__ W2, const float* __restrict__ b2,
                           float* __restrict__ out)
{
    int k = threadIdx.x;  // 32 threads, lanes 16..31 inert
    float p = -INFINITY;
    if (k < HIDDEN) {
        float acc = 0.f;
#pragma unroll
        for (int j = 0; j < HIDDEN; j++) acc += d_s[j] * W2[j * HIDDEN + k];
        p = acc * (1.0f / (float)N_NODES) + b2[k];
    }
    float m = p;
#pragma unroll
    for (int off = 16; off > 0; off >>= 1)
        m = fmaxf(m, __shfl_xor_sync(0xffffffffu, m, off));
    float e = (k < HIDDEN) ? expf(p - m) : 0.f;
    float ssum = e;
#pragma unroll
    for (int off = 16; off > 0; off >>= 1)
        ssum += __shfl_xor_sync(0xffffffffu, ssum, off);
    if (k < HIDDEN) out[k] = e / ssum;
}

extern "C" void kernel_launch(void* const* d_in, const int* in_sizes, int n_in,
                              void* d_out, int out_size)
{
    const float* x  = (const float*)d_in[0];
    const int*   ei = (const int*)d_in[1];     // [2, E] row-major
    const float* W1 = (const float*)d_in[2];
    const float* b1 = (const float*)d_in[3];
    const float* W2 = (const float*)d_in[4];
    const float* b2 = (const float*)d_in[5];
    const int* src = ei;
    const int* dst = ei + N_EDGES;
    float* out = (float*)d_out;

    zero_kernel<<<((N_NODES * HIDDEN / 4) + 255) / 256, 256>>>();
    hist_kernel<<<((N_EDGES / 4) + 255) / 256, 256>>>((const int4*)dst);
    dinv_kernel<<<(N_NODES + 255) / 256, 256>>>();
    gemm_kernel<<<(N_NODES + 255) / 256, 256>>>(x, W1);
    edge_kernel<<<(N_EDGES + 255) / 256, 256>>>(src, dst);
    finalize_kernel<<<(N_NODES + 255) / 256, 256>>>(b1);
    out_kernel<<<1, 32>>>(W2, b2, out);
}

// round 5
// speedup vs baseline: 1.8552x; 1.8552x over previous
#include <cuda_runtime.h>
#include <math.h>

#define N_NODES 100000
#define N_EDGES 3200000
#define N_FEAT  512
#define HIDDEN  16
#define SCAN_BLOCKS 98   // ceil(100000/1024)

typedef unsigned long long ull;

// ---- scratch (device globals; no runtime allocation) ----
__device__ float d_g[(size_t)N_NODES * HIDDEN];    // dinv[n] * (x[n] @ W1)
__device__ int   d_deg[N_NODES];
__device__ float d_dinv[N_NODES];
__device__ float d_csrc[N_NODES];                  // sum over out-edges of dinv[dst]
__device__ float d_s[HIDDEN];                      // sum_n c[n] * r[n]
__device__ int   d_rowstart[N_NODES + 1];          // CSR row starts (by dst)
__device__ int   d_cursor[N_NODES];                // fill cursors
__device__ int   d_esrc[N_EDGES];                  // CSR: src of each in-edge
__device__ int   d_bsum[SCAN_BLOCKS];
__device__ int   d_boff[SCAN_BLOCKS];

// ---- PTX helpers ----
__device__ __forceinline__ ull pack2(float x, float y) {
    ull r; asm("mov.b64 %0, {%1, %2};" : "=l"(r) : "f"(x), "f"(y)); return r;
}
__device__ __forceinline__ void unpack2(ull v, float& x, float& y) {
    asm("mov.b64 {%0, %1}, %2;" : "=f"(x), "=f"(y) : "l"(v));
}
__device__ __forceinline__ void fma2(ull& acc, ull a, ull b) {
    asm("fma.rn.f32x2 %0, %1, %2, %0;" : "+l"(acc) : "l"(a), "l"(b));
}
__device__ __forceinline__ void add2(ull& a, ull b) {
    asm("add.rn.f32x2 %0, %0, %1;" : "+l"(a) : "l"(b));
}

// ---- K0: zero scratch ----
__global__ void zero_kernel() {
    int i = blockIdx.x * blockDim.x + threadIdx.x;
    if (i < N_NODES) { d_deg[i] = 0; d_csrc[i] = 0.f; }
    if (i < HIDDEN)  { d_s[i] = 0.f; }
}

// ---- K1: in-degree histogram over dst (4 edges/thread) ----
__global__ void hist_kernel(const int4* __restrict__ dst4) {
    int i = blockIdx.x * blockDim.x + threadIdx.x;
    if (i < N_EDGES / 4) {
        int4 d = dst4[i];
        atomicAdd(&d_deg[d.x], 1);
        atomicAdd(&d_deg[d.y], 1);
        atomicAdd(&d_deg[d.z], 1);
        atomicAdd(&d_deg[d.w], 1);
    }
}

// ---- K2: dinv = rsqrt(deg + 1)  (self-loop included) ----
__global__ void dinv_kernel() {
    int n = blockIdx.x * blockDim.x + threadIdx.x;
    if (n < N_NODES) d_dinv[n] = rsqrtf((float)(d_deg[n] + 1));
}

// ---- K3a: per-block exclusive scan of deg (1024/block) ----
__global__ void scan1_kernel() {
    __shared__ int sh[1024];
    int t = threadIdx.x;
    int i = blockIdx.x * 1024 + t;
    int v = (i < N_NODES) ? d_deg[i] : 0;
    sh[t] = v;
    __syncthreads();
#pragma unroll
    for (int off = 1; off < 1024; off <<= 1) {
        int add = (t >= off) ? sh[t - off] : 0;
        __syncthreads();
        sh[t] += add;
        __syncthreads();
    }
    int incl = sh[t];
    if (i < N_NODES) d_rowstart[i] = incl - v;      // exclusive within block
    if (t == 1023) d_bsum[blockIdx.x] = incl;       // block total
}

// ---- K3b: scan the 98 block sums (one block) ----
__global__ void scan2_kernel() {
    __shared__ int sh[128];
    int t = threadIdx.x;
    sh[t] = (t < SCAN_BLOCKS) ? d_bsum[t] : 0;
    __syncthreads();
#pragma unroll
    for (int off = 1; off < 128; off <<= 1) {
        int add = (t >= off) ? sh[t - off] : 0;
        __syncthreads();
        sh[t] += add;
        __syncthreads();
    }
    if (t < SCAN_BLOCKS) d_boff[t] = sh[t] - d_bsum[t];  // exclusive
}

// ---- K3c: add block offsets; init cursors; sentinel ----
__global__ void scan3_kernel() {
    int i = blockIdx.x * 1024 + threadIdx.x;
    if (i < N_NODES) {
        int r = d_rowstart[i] + d_boff[blockIdx.x];
        d_rowstart[i] = r;
        d_cursor[i] = r;
    }
    if (i == 0) d_rowstart[N_NODES] = N_EDGES;
}

// ---- K4: fill CSR + csrc ----
__global__ void fill_kernel(const int* __restrict__ src, const int* __restrict__ dst) {
    int e = blockIdx.x * blockDim.x + threadIdx.x;
    if (e >= N_EDGES) return;
    int s = src[e];
    int d = dst[e];
    int slot = atomicAdd(&d_cursor[d], 1);
    d_esrc[slot] = s;
    atomicAdd(&d_csrc[s], d_dinv[d]);
}

// ---- K5: g[n] = dinv[n] * (x[n] @ W1) ----
// Warp = 16 nodes. Lane: q = lane&3 (k-quarter), g = lane>>2 (node pair 2g, 2g+1).
// Loads are 64B-contiguous per row (nL=8 vs 32 before); W in smem with pitch-9
// ull padding so the 4 distinct per-q addresses hit 4 distinct banks.
__global__ __launch_bounds__(256) void gemm_kernel(
    const float* __restrict__ x, const float* __restrict__ W1)
{
    __shared__ ull sW[N_FEAT * 9];                // pitch 9 ull per k-row, 36 KB
    const ull* Wg = (const ull*)W1;               // [512][8] ull
    for (int i = threadIdx.x; i < N_FEAT * 8; i += 256)
        sW[(i >> 3) * 9 + (i & 7)] = Wg[i];
    __syncthreads();

    int lane = threadIdx.x & 31;
    int warp = threadIdx.x >> 5;
    int q = lane & 3;
    int g = lane >> 2;
    int node0 = blockIdx.x * 128 + warp * 16 + g * 2;

    int na = min(node0, N_NODES - 1);
    int nb = min(node0 + 1, N_NODES - 1);
    const float4* ra = (const float4*)(x + (size_t)na * N_FEAT);
    const float4* rb = (const float4*)(x + (size_t)nb * N_FEAT);

    ull acc[2][8];
#pragma unroll
    for (int m = 0; m < 8; m++) { acc[0][m] = 0ull; acc[1][m] = 0ull; }

#pragma unroll 2
    for (int i = 0; i < 32; i++) {
        int j = (i << 2) + q;                     // float4 index within row
        float4 xa = ra[j];
        float4 xb = rb[j];
        const ull* wr = sW + (size_t)(j << 2) * 9;
#pragma unroll
        for (int t = 0; t < 4; t++) {
            float xat = (t == 0) ? xa.x : (t == 1) ? xa.y : (t == 2) ? xa.z : xa.w;
            float xbt = (t == 0) ? xb.x : (t == 1) ? xb.y : (t == 2) ? xb.z : xb.w;
            ull xaa = pack2(xat, xat);
            ull xbb = pack2(xbt, xbt);
            const ull* w = wr + t * 9;
#pragma unroll
            for (int m = 0; m < 8; m++) {
                ull wv = w[m];
                fma2(acc[0][m], xaa, wv);
                fma2(acc[1][m], xbb, wv);
            }
        }
    }

    // reduce over the 4 k-quarter lanes (xor 1, 2 within each 4-lane group)
#pragma unroll
    for (int st = 1; st <= 2; st <<= 1) {
#pragma unroll
        for (int p = 0; p < 2; p++)
#pragma unroll
            for (int m = 0; m < 8; m++) {
                ull o = __shfl_xor_sync(0xffffffffu, acc[p][m], st);
                add2(acc[p][m], o);
            }
    }

    if (q < 2) {
        int n = node0 + q;
        if (n < N_NODES) {
            float dv = d_dinv[n];
            float4* out = (float4*)(d_g + (size_t)n * HIDDEN);
#pragma unroll
            for (int m4 = 0; m4 < 4; m4++) {
                float a, b, c, d;
                unpack2(acc[q][2 * m4], a, b);
                unpack2(acc[q][2 * m4 + 1], c, d);
                out[m4] = make_float4(a * dv, b * dv, c * dv, d * dv);
            }
        }
    }
}

// ---- K6: fused CSR aggregate + finalize + global reduce ----
// 2 threads per node (h = feature half), 32B-aligned gathers (full sectors).
__global__ __launch_bounds__(256) void aggfin_kernel(const float* __restrict__ b1) {
    int tid = threadIdx.x;
    int h = tid & 1;
    int node = blockIdx.x * 128 + (tid >> 1);

    float cr[8];
#pragma unroll
    for (int j = 0; j < 8; j++) cr[j] = 0.f;

    if (node < N_NODES) {
        const float4* gb = (const float4*)d_g;
        int beg = d_rowstart[node];
        int end = d_rowstart[node + 1];
        float4 a0 = make_float4(0.f, 0.f, 0.f, 0.f);
        float4 a1 = make_float4(0.f, 0.f, 0.f, 0.f);
#pragma unroll 2
        for (int j = beg; j < end; j++) {
            int s = d_esrc[j];
            size_t base = (size_t)s * 4 + h * 2;
            float4 v0 = gb[base];
            float4 v1 = gb[base + 1];
            a0.x += v0.x; a0.y += v0.y; a0.z += v0.z; a0.w += v0.w;
            a1.x += v1.x; a1.y += v1.y; a1.z += v1.z; a1.w += v1.w;
        }
        // self-loop (g already scaled by dinv[node])
        {
            size_t base = (size_t)node * 4 + h * 2;
            float4 v0 = gb[base];
            float4 v1 = gb[base + 1];
            a0.x += v0.x; a0.y += v0.y; a0.z += v0.z; a0.w += v0.w;
            a1.x += v1.x; a1.y += v1.y; a1.z += v1.z; a1.w += v1.w;
        }
        float dv = d_dinv[node];
        float c = dv * (dv + d_csrc[node]);
        const float4* bb4 = (const float4*)b1;
        float4 b0 = bb4[2 * h], bq1 = bb4[2 * h + 1];
        cr[0] = c * fmaxf(fmaf(dv, a0.x, b0.x), 0.f);
        cr[1] = c * fmaxf(fmaf(dv, a0.y, b0.y), 0.f);
        cr[2] = c * fmaxf(fmaf(dv, a0.z, b0.z), 0.f);
        cr[3] = c * fmaxf(fmaf(dv, a0.w, b0.w), 0.f);
        cr[4] = c * fmaxf(fmaf(dv, a1.x, bq1.x), 0.f);
        cr[5] = c * fmaxf(fmaf(dv, a1.y, bq1.y), 0.f);
        cr[6] = c * fmaxf(fmaf(dv, a1.z, bq1.z), 0.f);
        cr[7] = c * fmaxf(fmaf(dv, a1.w, bq1.w), 0.f);
    }

    // warp reduce across same-parity lanes (xor 2,4,8,16) -> lanes 0 (h=0), 1 (h=1)
#pragma unroll
    for (int j = 0; j < 8; j++) {
        float v = cr[j];
#pragma unroll
        for (int off = 2; off <= 16; off <<= 1)
            v += __shfl_xor_sync(0xffffffffu, v, off);
        cr[j] = v;
    }

    __shared__ float red[8][HIDDEN];
    int lane = tid & 31;
    int w = tid >> 5;
    if (lane < 2) {
#pragma unroll
        for (int j = 0; j < 8; j++) red[w][8 * lane + j] = cr[j];
    }
    __syncthreads();
    if (tid < HIDDEN) {
        float t = 0.f;
#pragma unroll
        for (int ww = 0; ww < 8; ww++) t += red[ww][tid];
        atomicAdd(&d_s[tid], t);
    }
}

// ---- K7: pooled = s@W2/N + b2 ; softmax ; write 16 floats ----
__global__ void out_kernel(const float* __restrict__ W2, const float* __restrict__ b2,
                           float* __restrict__ out)
{
    int k = threadIdx.x;
    float p = -INFINITY;
    if (k < HIDDEN) {
        float acc = 0.f;
#pragma unroll
        for (int j = 0; j < HIDDEN; j++) acc += d_s[j] * W2[j * HIDDEN + k];
        p = acc * (1.0f / (float)N_NODES) + b2[k];
    }
    float m = p;
#pragma unroll
    for (int off = 16; off > 0; off >>= 1)
        m = fmaxf(m, __shfl_xor_sync(0xffffffffu, m, off));
    float e = (k < HIDDEN) ? expf(p - m) : 0.f;
    float ssum = e;
#pragma unroll
    for (int off = 16; off > 0; off >>= 1)
        ssum += __shfl_xor_sync(0xffffffffu, ssum, off);
    if (k < HIDDEN) out[k] = e / ssum;
}

extern "C" void kernel_launch(void* const* d_in, const int* in_sizes, int n_in,
                              void* d_out, int out_size)
{
    const float* x  = (const float*)d_in[0];
    const int*   ei = (const int*)d_in[1];     // [2, E] row-major
    const float* W1 = (const float*)d_in[2];
    const float* b1 = (const float*)d_in[3];
    const float* W2 = (const float*)d_in[4];
    const float* b2 = (const float*)d_in[5];
    const int* src = ei;
    const int* dst = ei + N_EDGES;
    float* out = (float*)d_out;

    zero_kernel<<<(N_NODES + 255) / 256, 256>>>();
    hist_kernel<<<((N_EDGES / 4) + 255) / 256, 256>>>((const int4*)dst);
    dinv_kernel<<<(N_NODES + 255) / 256, 256>>>();
    scan1_kernel<<<SCAN_BLOCKS, 1024>>>();
    scan2_kernel<<<1, 128>>>();
    scan3_kernel<<<SCAN_BLOCKS, 1024>>>();
    fill_kernel<<<(N_EDGES + 255) / 256, 256>>>(src, dst);
    gemm_kernel<<<(N_NODES + 127) / 128, 256>>>(x, W1);
    aggfin_kernel<<<(N_NODES + 127) / 128, 256>>>(b1);
    out_kernel<<<1, 32>>>(W2, b2, out);
}

// round 6
// speedup vs baseline: 2.0349x; 1.0969x over previous
#include <cuda_runtime.h>
#include <math.h>

#define N_NODES 100000
#define N_EDGES 3200000
#define N_FEAT  512
#define HIDDEN  16
#define SCAN_BLOCKS 98   // ceil(100000/1024)

typedef unsigned long long ull;

// ---- scratch (device globals; no runtime allocation) ----
__device__ float d_g[(size_t)N_NODES * HIDDEN];    // dinv[n] * (x[n] @ W1)
__device__ int   d_deg[N_NODES];
__device__ float d_dinv[N_NODES];
__device__ float d_csrc[N_NODES];                  // sum over out-edges of dinv[dst]
__device__ float d_s[HIDDEN];                      // sum_n c[n] * r[n]
__device__ int   d_rowstart[N_NODES + 1];          // CSR row starts (by dst)
__device__ int   d_cursor[N_NODES];                // fill cursors
__device__ int   d_esrc[N_EDGES];                  // CSR: src of each in-edge
__device__ int   d_bsum[SCAN_BLOCKS];
__device__ int   d_boff[SCAN_BLOCKS];

// ---- PTX helpers ----
__device__ __forceinline__ unsigned f2tf32(float f) {
    unsigned u;
    asm("cvt.rna.tf32.f32 %0, %1;" : "=r"(u) : "f"(f));
    return u;
}
__device__ __forceinline__ void mma_tf32(float d[4], const unsigned a[4], unsigned b0, unsigned b1) {
    asm volatile(
        "mma.sync.aligned.m16n8k8.row.col.f32.tf32.tf32.f32 "
        "{%0,%1,%2,%3}, {%4,%5,%6,%7}, {%8,%9}, {%0,%1,%2,%3};"
        : "+f"(d[0]), "+f"(d[1]), "+f"(d[2]), "+f"(d[3])
        : "r"(a[0]), "r"(a[1]), "r"(a[2]), "r"(a[3]), "r"(b0), "r"(b1));
}

// ---- K0: zero scratch ----
__global__ void zero_kernel() {
    int i = blockIdx.x * blockDim.x + threadIdx.x;
    if (i < N_NODES) { d_deg[i] = 0; d_csrc[i] = 0.f; }
    if (i < HIDDEN)  { d_s[i] = 0.f; }
}

// ---- K1: in-degree histogram over dst (4 edges/thread) ----
__global__ void hist_kernel(const int4* __restrict__ dst4) {
    int i = blockIdx.x * blockDim.x + threadIdx.x;
    if (i < N_EDGES / 4) {
        int4 d = dst4[i];
        atomicAdd(&d_deg[d.x], 1);
        atomicAdd(&d_deg[d.y], 1);
        atomicAdd(&d_deg[d.z], 1);
        atomicAdd(&d_deg[d.w], 1);
    }
}

// ---- K2: per-block exclusive scan of deg + dinv (1024/block) ----
__global__ void scan1_kernel() {
    __shared__ int sh[1024];
    int t = threadIdx.x;
    int i = blockIdx.x * 1024 + t;
    int v = (i < N_NODES) ? d_deg[i] : 0;
    if (i < N_NODES) d_dinv[i] = rsqrtf((float)(v + 1));   // self-loop included
    sh[t] = v;
    __syncthreads();
#pragma unroll
    for (int off = 1; off < 1024; off <<= 1) {
        int add = (t >= off) ? sh[t - off] : 0;
        __syncthreads();
        sh[t] += add;
        __syncthreads();
    }
    int incl = sh[t];
    if (i < N_NODES) d_rowstart[i] = incl - v;      // exclusive within block
    if (t == 1023) d_bsum[blockIdx.x] = incl;       // block total
}

// ---- K3: scan the 98 block sums (one block) ----
__global__ void scan2_kernel() {
    __shared__ int sh[128];
    int t = threadIdx.x;
    sh[t] = (t < SCAN_BLOCKS) ? d_bsum[t] : 0;
    __syncthreads();
#pragma unroll
    for (int off = 1; off < 128; off <<= 1) {
        int add = (t >= off) ? sh[t - off] : 0;
        __syncthreads();
        sh[t] += add;
        __syncthreads();
    }
    if (t < SCAN_BLOCKS) d_boff[t] = sh[t] - d_bsum[t];  // exclusive
}

// ---- K4: add block offsets; init cursors; sentinel ----
__global__ void scan3_kernel() {
    int i = blockIdx.x * 1024 + threadIdx.x;
    if (i < N_NODES) {
        int r = d_rowstart[i] + d_boff[blockIdx.x];
        d_rowstart[i] = r;
        d_cursor[i] = r;
    }
    if (i == 0) d_rowstart[N_NODES] = N_EDGES;
}

// ---- K5: fill CSR + csrc (4 edges/thread) ----
__global__ void fill_kernel(const int4* __restrict__ src4, const int4* __restrict__ dst4) {
    int i = blockIdx.x * blockDim.x + threadIdx.x;
    if (i >= N_EDGES / 4) return;
    int4 s4 = src4[i];
    int4 d4 = dst4[i];
#pragma unroll
    for (int u = 0; u < 4; u++) {
        int s = (u == 0) ? s4.x : (u == 1) ? s4.y : (u == 2) ? s4.z : s4.w;
        int d = (u == 0) ? d4.x : (u == 1) ? d4.y : (u == 2) ? d4.z : d4.w;
        int slot = atomicAdd(&d_cursor[d], 1);
        d_esrc[slot] = s;
        atomicAdd(&d_csrc[s], d_dinv[d]);
    }
}

// ---- K6: g = dinv * (x @ W1) via tf32 tensor cores, split-W for precision ----
// Block = 8 warps = 256 nodes. Warp = 32 nodes (2 m16 tiles) x 16 out (2 n8
// tiles), K=512 = 64 k-steps of k8. W fragments (hi+lo tf32 split) prepacked
// into dynamic smem: one LDS.128 per k-step per table, conflict-free.
__global__ __launch_bounds__(256) void gemm_kernel(
    const float* __restrict__ x, const float* __restrict__ W1)
{
    extern __shared__ unsigned dynsmem[];
    unsigned* sWhi = dynsmem;           // [64 ksteps][32 lanes][4] = 8192 u32
    unsigned* sWlo = dynsmem + 8192;

    // prepack B fragments: entry i = ((ks*32 + lane)*4 + s)
    // s: 0=b0_n0, 1=b1_n0, 2=b0_n1, 3=b1_n1
    for (int i = threadIdx.x; i < 8192; i += 256) {
        int s    = i & 3;
        int lane = (i >> 2) & 31;
        int ks   = i >> 7;
        int tig  = lane & 3;
        int gid  = lane >> 2;
        float w = W1[(ks * 8 + tig + (s & 1) * 4) * 16 + (s >> 1) * 8 + gid];
        unsigned hi = f2tf32(w);
        float lof = w - __uint_as_float(hi);
        sWhi[i] = hi;
        sWlo[i] = f2tf32(lof);
    }
    __syncthreads();

    int lane = threadIdx.x & 31;
    int warp = threadIdx.x >> 5;
    int tig = lane & 3;
    int gid = lane >> 2;
    int node0 = (blockIdx.x * 8 + warp) * 32;
    if (node0 >= N_NODES) return;   // tail warps (grid covers exactly; guard anyway)

    const float* pA = x + (size_t)(node0 + gid) * N_FEAT + tig;
    const size_t R8 = (size_t)8 * N_FEAT;

    float acc[2][2][4];
#pragma unroll
    for (int mt = 0; mt < 2; mt++)
#pragma unroll
        for (int nt = 0; nt < 2; nt++)
#pragma unroll
            for (int r = 0; r < 4; r++) acc[mt][nt][r] = 0.f;

#pragma unroll 2
    for (int ks = 0; ks < 64; ks++) {
        int off = ks * 8;
        unsigned a0[4], a1[4];
        a0[0] = f2tf32(pA[off]);
        a0[1] = f2tf32(pA[off + R8]);
        a0[2] = f2tf32(pA[off + 4]);
        a0[3] = f2tf32(pA[off + 4 + R8]);
        a1[0] = f2tf32(pA[off + 2 * R8]);
        a1[1] = f2tf32(pA[off + 3 * R8]);
        a1[2] = f2tf32(pA[off + 4 + 2 * R8]);
        a1[3] = f2tf32(pA[off + 4 + 3 * R8]);

        uint4 bh = ((const uint4*)sWhi)[ks * 32 + lane];
        uint4 bl = ((const uint4*)sWlo)[ks * 32 + lane];

        mma_tf32(acc[0][0], a0, bh.x, bh.y);
        mma_tf32(acc[0][1], a0, bh.z, bh.w);
        mma_tf32(acc[1][0], a1, bh.x, bh.y);
        mma_tf32(acc[1][1], a1, bh.z, bh.w);
        mma_tf32(acc[0][0], a0, bl.x, bl.y);
        mma_tf32(acc[0][1], a0, bl.z, bl.w);
        mma_tf32(acc[1][0], a1, bl.x, bl.y);
        mma_tf32(acc[1][1], a1, bl.z, bl.w);
    }

    // epilogue: scale by dinv, store float2 pairs
#pragma unroll
    for (int mt = 0; mt < 2; mt++) {
        int rlo = node0 + mt * 16 + gid;
        int rhi = rlo + 8;
        float dvl = d_dinv[rlo];
        float dvh = d_dinv[rhi];
#pragma unroll
        for (int nt = 0; nt < 2; nt++) {
            int col = nt * 8 + 2 * tig;
            float2 vlo = make_float2(acc[mt][nt][0] * dvl, acc[mt][nt][1] * dvl);
            float2 vhi = make_float2(acc[mt][nt][2] * dvh, acc[mt][nt][3] * dvh);
            *(float2*)(d_g + (size_t)rlo * HIDDEN + col) = vlo;
            *(float2*)(d_g + (size_t)rhi * HIDDEN + col) = vhi;
        }
    }
}

// ---- K7: fused CSR aggregate + finalize + global reduce ----
// 4 lanes per node (h = feature quarter, 16B each); warp spans 8 nodes.
__global__ __launch_bounds__(256) void aggfin_kernel(const float* __restrict__ b1) {
    int tid = threadIdx.x;
    int h = tid & 3;
    int node = blockIdx.x * 64 + (tid >> 2);

    float4 cr = make_float4(0.f, 0.f, 0.f, 0.f);

    if (node < N_NODES) {
        const float4* gb = (const float4*)d_g;
        int beg = d_rowstart[node];
        int end = d_rowstart[node + 1];
        float4 a = make_float4(0.f, 0.f, 0.f, 0.f);
#pragma unroll 2
        for (int j = beg; j < end; j++) {
            int s = d_esrc[j];
            float4 v = gb[(size_t)s * 4 + h];
            a.x += v.x; a.y += v.y; a.z += v.z; a.w += v.w;
        }
        // self-loop (g already scaled by dinv[node])
        {
            float4 v = gb[(size_t)node * 4 + h];
            a.x += v.x; a.y += v.y; a.z += v.z; a.w += v.w;
        }
        float dv = d_dinv[node];
        float c = dv * (dv + d_csrc[node]);
        float4 bb = ((const float4*)b1)[h];
        cr.x = c * fmaxf(fmaf(dv, a.x, bb.x), 0.f);
        cr.y = c * fmaxf(fmaf(dv, a.y, bb.y), 0.f);
        cr.z = c * fmaxf(fmaf(dv, a.z, bb.z), 0.f);
        cr.w = c * fmaxf(fmaf(dv, a.w, bb.w), 0.f);
    }

    // reduce across the 8 nodes in the warp (lanes with same h)
#pragma unroll
    for (int off = 4; off <= 16; off <<= 1) {
        cr.x += __shfl_xor_sync(0xffffffffu, cr.x, off);
        cr.y += __shfl_xor_sync(0xffffffffu, cr.y, off);
        cr.z += __shfl_xor_sync(0xffffffffu, cr.z, off);
        cr.w += __shfl_xor_sync(0xffffffffu, cr.w, off);
    }

    __shared__ float4 red[8][4];
    int lane = tid & 31;
    int w = tid >> 5;
    if (lane < 4) red[w][lane] = cr;   // lane == h for lanes 0..3
    __syncthreads();
    if (tid < HIDDEN) {
        float t = 0.f;
#pragma unroll
        for (int ww = 0; ww < 8; ww++) t += ((const float*)&red[ww][0])[tid];
        atomicAdd(&d_s[tid], t);
    }
}

// ---- K8: pooled = s@W2/N + b2 ; softmax ; write 16 floats ----
__global__ void out_kernel(const float* __restrict__ W2, const float* __restrict__ b2,
                           float* __restrict__ out)
{
    int k = threadIdx.x;
    float p = -INFINITY;
    if (k < HIDDEN) {
        float acc = 0.f;
#pragma unroll
        for (int j = 0; j < HIDDEN; j++) acc += d_s[j] * W2[j * HIDDEN + k];
        p = acc * (1.0f / (float)N_NODES) + b2[k];
    }
    float m = p;
#pragma unroll
    for (int off = 16; off > 0; off >>= 1)
        m = fmaxf(m, __shfl_xor_sync(0xffffffffu, m, off));
    float e = (k < HIDDEN) ? expf(p - m) : 0.f;
    float ssum = e;
#pragma unroll
    for (int off = 16; off > 0; off >>= 1)
        ssum += __shfl_xor_sync(0xffffffffu, ssum, off);
    if (k < HIDDEN) out[k] = e / ssum;
}

extern "C" void kernel_launch(void* const* d_in, const int* in_sizes, int n_in,
                              void* d_out, int out_size)
{
    const float* x  = (const float*)d_in[0];
    const int*   ei = (const int*)d_in[1];     // [2, E] row-major
    const float* W1 = (const float*)d_in[2];
    const float* b1 = (const float*)d_in[3];
    const float* W2 = (const float*)d_in[4];
    const float* b2 = (const float*)d_in[5];
    const int* src = ei;
    const int* dst = ei + N_EDGES;
    float* out = (float*)d_out;

    cudaFuncSetAttribute(gemm_kernel, cudaFuncAttributeMaxDynamicSharedMemorySize,
                         2 * 8192 * sizeof(unsigned));

    zero_kernel<<<(N_NODES + 255) / 256, 256>>>();
    hist_kernel<<<((N_EDGES / 4) + 255) / 256, 256>>>((const int4*)dst);
    scan1_kernel<<<SCAN_BLOCKS, 1024>>>();
    scan2_kernel<<<1, 128>>>();
    scan3_kernel<<<SCAN_BLOCKS, 1024>>>();
    fill_kernel<<<((N_EDGES / 4) + 255) / 256, 256>>>((const int4*)src, (const int4*)dst);
    gemm_kernel<<<(N_NODES + 255) / 256, 256, 2 * 8192 * sizeof(unsigned)>>>(x, W1);
    aggfin_kernel<<<(N_NODES + 63) / 64, 256>>>(b1);
    out_kernel<<<1, 32>>>(W2, b2, out);
}

// round 8
// speedup vs baseline: 2.6655x; 1.3099x over previous
#include <cuda_runtime.h>
#include <math.h>

#define N_NODES 100000
#define N_EDGES 3200000
#define N_FEAT  512
#define HIDDEN  16
#define SCAN_BLOCKS 98   // ceil(100000/1024)

typedef unsigned long long ull;

// ---- scratch (device globals; no runtime allocation) ----
__device__ float d_g[(size_t)N_NODES * HIDDEN];    // dinv[n] * (x[n] @ W1)
__device__ int   d_deg[N_NODES];
__device__ float d_dinv[N_NODES];
__device__ float d_csrc[N_NODES];                  // sum over out-edges of dinv[dst]
__device__ float d_s[HIDDEN];                      // sum_n c[n] * r[n]
__device__ int   d_rowstart[N_NODES + 1];          // CSR row starts (by dst)
__device__ int   d_cursor[N_NODES];                // fill cursors
__device__ int   d_esrc[N_EDGES];                  // CSR: src of each in-edge
__device__ int   d_bsum[SCAN_BLOCKS];

// ---- PTX helpers ----
__device__ __forceinline__ unsigned f2tf32(float f) {
    unsigned u;
    asm("cvt.rna.tf32.f32 %0, %1;" : "=r"(u) : "f"(f));
    return u;
}
__device__ __forceinline__ void mma_tf32(float d[4], const unsigned a[4], unsigned b0, unsigned b1) {
    asm volatile(
        "mma.sync.aligned.m16n8k8.row.col.f32.tf32.tf32.f32 "
        "{%0,%1,%2,%3}, {%4,%5,%6,%7}, {%8,%9}, {%0,%1,%2,%3};"
        : "+f"(d[0]), "+f"(d[1]), "+f"(d[2]), "+f"(d[3])
        : "r"(a[0]), "r"(a[1]), "r"(a[2]), "r"(a[3]), "r"(b0), "r"(b1));
}

// ---- K0: zero scratch ----
__global__ void zero_kernel() {
    int i = blockIdx.x * blockDim.x + threadIdx.x;
    if (i < N_NODES) { d_deg[i] = 0; d_csrc[i] = 0.f; }
    if (i < HIDDEN)  { d_s[i] = 0.f; }
}

// ---- K1: in-degree histogram over dst (4 edges/thread) ----
__global__ void hist_kernel(const int4* __restrict__ dst4) {
    int i = blockIdx.x * blockDim.x + threadIdx.x;
    if (i < N_EDGES / 4) {
        int4 d = dst4[i];
        atomicAdd(&d_deg[d.x], 1);
        atomicAdd(&d_deg[d.y], 1);
        atomicAdd(&d_deg[d.z], 1);
        atomicAdd(&d_deg[d.w], 1);
    }
}

// ---- K2: per-block exclusive scan of deg + dinv (1024/block) ----
__global__ void scan1_kernel() {
    __shared__ int sh[1024];
    int t = threadIdx.x;
    int i = blockIdx.x * 1024 + t;
    int v = (i < N_NODES) ? d_deg[i] : 0;
    if (i < N_NODES) d_dinv[i] = rsqrtf((float)(v + 1));   // self-loop included
    sh[t] = v;
    __syncthreads();
#pragma unroll
    for (int off = 1; off < 1024; off <<= 1) {
        int add = (t >= off) ? sh[t - off] : 0;
        __syncthreads();
        sh[t] += add;
        __syncthreads();
    }
    int incl = sh[t];
    if (i < N_NODES) d_rowstart[i] = incl - v;      // exclusive within block
    if (t == 1023) d_bsum[blockIdx.x] = incl;       // block total
}

// ---- K3: fused block-offset scan + apply + cursor init + sentinel ----
// Each block redundantly scans the 98 block sums in smem (cheap), then applies.
__global__ void scan23_kernel() {
    __shared__ int sb[128];
    int t = threadIdx.x;
    if (t < 128) sb[t] = (t < SCAN_BLOCKS) ? d_bsum[t] : 0;
    __syncthreads();
#pragma unroll
    for (int off = 1; off < 128; off <<= 1) {
        int add = (t < 128 && t >= off) ? sb[t - off] : 0;
        __syncthreads();
        if (t < 128) sb[t] += add;
        __syncthreads();
    }
    int boff = (blockIdx.x > 0) ? sb[blockIdx.x - 1] : 0;   // exclusive offset
    int i = blockIdx.x * 1024 + t;
    if (i < N_NODES) {
        int r = d_rowstart[i] + boff;
        d_rowstart[i] = r;
        d_cursor[i] = r;
    }
    if (i == 0) d_rowstart[N_NODES] = N_EDGES;
}

// ---- K4: fill CSR + csrc (4 edges/thread) ----
__global__ void fill_kernel(const int4* __restrict__ src4, const int4* __restrict__ dst4) {
    int i = blockIdx.x * blockDim.x + threadIdx.x;
    if (i >= N_EDGES / 4) return;
    int4 s4 = src4[i];
    int4 d4 = dst4[i];
#pragma unroll
    for (int u = 0; u < 4; u++) {
        int s = (u == 0) ? s4.x : (u == 1) ? s4.y : (u == 2) ? s4.z : s4.w;
        int d = (u == 0) ? d4.x : (u == 1) ? d4.y : (u == 2) ? d4.z : d4.w;
        int slot = atomicAdd(&d_cursor[d], 1);
        d_esrc[slot] = s;
        atomicAdd(&d_csrc[s], d_dinv[d]);
    }
}

// ---- K5: g = dinv * (x @ W1), tf32 MMA, split-W, k-permuted coalesced loads ----
// Warp = 32 nodes x 16 outputs. Per k16 chunk each thread loads one float4 per
// row (fully coalesced 64B/row warp segments). The k-order inside each k8 MMA
// step is permuted; B prepack applies the SAME permutation, so the dot product
// is unchanged:  col_k = (ks>>1)*16 + 4*tig + (ks&1)*2 + b_slot.
__global__ __launch_bounds__(256) void gemm_kernel(
    const float* __restrict__ x, const float* __restrict__ W1)
{
    extern __shared__ unsigned dynsmem[];
    unsigned* sWhi = dynsmem;           // [64 ksteps][32 lanes][4] = 8192 u32
    unsigned* sWlo = dynsmem + 8192;

    for (int i = threadIdx.x; i < 8192; i += 256) {
        int s    = i & 3;               // 0=b0n0 1=b1n0 2=b0n1 3=b1n1
        int lane = (i >> 2) & 31;
        int ks   = i >> 7;
        int tig  = lane & 3;
        int gid  = lane >> 2;
        int col_k = (ks >> 1) * 16 + 4 * tig + (ks & 1) * 2 + (s & 1);
        int col_n = (s >> 1) * 8 + gid;
        float w = W1[col_k * 16 + col_n];
        unsigned hi = f2tf32(w);
        float lof = w - __uint_as_float(hi);
        sWhi[i] = hi;
        sWlo[i] = f2tf32(lof);
    }
    __syncthreads();

    int lane = threadIdx.x & 31;
    int warp = threadIdx.x >> 5;
    int tig = lane & 3;
    int gid = lane >> 2;
    int node0 = (blockIdx.x * 8 + warp) * 32;
    if (node0 >= N_NODES) return;       // tail warps (after prepack + sync)

    const float* pr = x + (size_t)(node0 + gid) * N_FEAT;
    const size_t R8 = (size_t)8 * N_FEAT;

    float acc[2][2][4];
#pragma unroll
    for (int mt = 0; mt < 2; mt++)
#pragma unroll
        for (int nt = 0; nt < 2; nt++)
#pragma unroll
            for (int r = 0; r < 4; r++) acc[mt][nt][r] = 0.f;

#pragma unroll 2
    for (int kc = 0; kc < 32; kc++) {
        int cb = kc * 16 + 4 * tig;
        float4 xa = *(const float4*)(pr + cb);                // row gid
        float4 xb = *(const float4*)(pr + R8 + cb);           // row gid+8
        float4 xc = *(const float4*)(pr + 2 * R8 + cb);       // row gid+16
        float4 xd = *(const float4*)(pr + 3 * R8 + cb);       // row gid+24

        uint4 bh0 = ((const uint4*)sWhi)[(2 * kc) * 32 + lane];
        uint4 bl0 = ((const uint4*)sWlo)[(2 * kc) * 32 + lane];
        uint4 bh1 = ((const uint4*)sWhi)[(2 * kc + 1) * 32 + lane];
        uint4 bl1 = ((const uint4*)sWlo)[(2 * kc + 1) * 32 + lane];

        // k-step 2kc: cols cb+0 (slot k=tig), cb+1 (slot k=tig+4)
        unsigned a0[4] = { f2tf32(xa.x), f2tf32(xb.x), f2tf32(xa.y), f2tf32(xb.y) };
        unsigned a1[4] = { f2tf32(xc.x), f2tf32(xd.x), f2tf32(xc.y), f2tf32(xd.y) };
        mma_tf32(acc[0][0], a0, bh0.x, bh0.y);
        mma_tf32(acc[0][1], a0, bh0.z, bh0.w);
        mma_tf32(acc[1][0], a1, bh0.x, bh0.y);
        mma_tf32(acc[1][1], a1, bh0.z, bh0.w);
        mma_tf32(acc[0][0], a0, bl0.x, bl0.y);
        mma_tf32(acc[0][1], a0, bl0.z, bl0.w);
        mma_tf32(acc[1][0], a1, bl0.x, bl0.y);
        mma_tf32(acc[1][1], a1, bl0.z, bl0.w);

        // k-step 2kc+1: cols cb+2, cb+3
        unsigned c0[4] = { f2tf32(xa.z), f2tf32(xb.z), f2tf32(xa.w), f2tf32(xb.w) };
        unsigned c1[4] = { f2tf32(xc.z), f2tf32(xd.z), f2tf32(xc.w), f2tf32(xd.w) };
        mma_tf32(acc[0][0], c0, bh1.x, bh1.y);
        mma_tf32(acc[0][1], c0, bh1.z, bh1.w);
        mma_tf32(acc[1][0], c1, bh1.x, bh1.y);
        mma_tf32(acc[1][1], c1, bh1.z, bh1.w);
        mma_tf32(acc[0][0], c0, bl1.x, bl1.y);
        mma_tf32(acc[0][1], c0, bl1.z, bl1.w);
        mma_tf32(acc[1][0], c1, bl1.x, bl1.y);
        mma_tf32(acc[1][1], c1, bl1.z, bl1.w);
    }

    // epilogue: scale by dinv, store float2 pairs
#pragma unroll
    for (int mt = 0; mt < 2; mt++) {
        int rlo = node0 + mt * 16 + gid;
        int rhi = rlo + 8;
        float dvl = d_dinv[rlo];
        float dvh = d_dinv[rhi];
#pragma unroll
        for (int nt = 0; nt < 2; nt++) {
            int col = nt * 8 + 2 * tig;
            float2 vlo = make_float2(acc[mt][nt][0] * dvl, acc[mt][nt][1] * dvl);
            float2 vhi = make_float2(acc[mt][nt][2] * dvh, acc[mt][nt][3] * dvh);
            *(float2*)(d_g + (size_t)rlo * HIDDEN + col) = vlo;
            *(float2*)(d_g + (size_t)rhi * HIDDEN + col) = vhi;
        }
    }
}

// ---- K6: fused CSR aggregate + finalize + global reduce ----
// 4 lanes per node (h = feature quarter); pairwise-unrolled gather for MLP.
__global__ __launch_bounds__(256) void aggfin_kernel(const float* __restrict__ b1) {
    int tid = threadIdx.x;
    int h = tid & 3;
    int node = blockIdx.x * 64 + (tid >> 2);

    float4 cr = make_float4(0.f, 0.f, 0.f, 0.f);

    if (node < N_NODES) {
        const float4* gb = (const float4*)d_g;
        int beg = d_rowstart[node];
        int end = d_rowstart[node + 1];
        float4 a = make_float4(0.f, 0.f, 0.f, 0.f);
        float4 b = make_float4(0.f, 0.f, 0.f, 0.f);
        int j = beg;
        for (; j + 2 <= end; j += 2) {
            int s0 = d_esrc[j];
            int s1 = d_esrc[j + 1];
            float4 v0 = gb[(size_t)s0 * 4 + h];
            float4 v1 = gb[(size_t)s1 * 4 + h];
            a.x += v0.x; a.y += v0.y; a.z += v0.z; a.w += v0.w;
            b.x += v1.x; b.y += v1.y; b.z += v1.z; b.w += v1.w;
        }
        if (j < end) {
            int s0 = d_esrc[j];
            float4 v0 = gb[(size_t)s0 * 4 + h];
            a.x += v0.x; a.y += v0.y; a.z += v0.z; a.w += v0.w;
        }
        // self-loop (g already scaled by dinv[node])
        {
            float4 v = gb[(size_t)node * 4 + h];
            a.x += v.x; a.y += v.y; a.z += v.z; a.w += v.w;
        }
        a.x += b.x; a.y += b.y; a.z += b.z; a.w += b.w;
        float dv = d_dinv[node];
        float c = dv * (dv + d_csrc[node]);
        float4 bb = ((const float4*)b1)[h];
        cr.x = c * fmaxf(fmaf(dv, a.x, bb.x), 0.f);
        cr.y = c * fmaxf(fmaf(dv, a.y, bb.y), 0.f);
        cr.z = c * fmaxf(fmaf(dv, a.z, bb.z), 0.f);
        cr.w = c * fmaxf(fmaf(dv, a.w, bb.w), 0.f);
    }

    // reduce across the 8 nodes in the warp (lanes with same h)
#pragma unroll
    for (int off = 4; off <= 16; off <<= 1) {
        cr.x += __shfl_xor_sync(0xffffffffu, cr.x, off);
        cr.y += __shfl_xor_sync(0xffffffffu, cr.y, off);
        cr.z += __shfl_xor_sync(0xffffffffu, cr.z, off);
        cr.w += __shfl_xor_sync(0xffffffffu, cr.w, off);
    }

    __shared__ float4 red[8][4];
    int lane = tid & 31;
    int w = tid >> 5;
    if (lane < 4) red[w][lane] = cr;   // lane == h for lanes 0..3
    __syncthreads();
    if (tid < HIDDEN) {
        float t = 0.f;
#pragma unroll
        for (int ww = 0; ww < 8; ww++) t += ((const float*)&red[ww][0])[tid];
        atomicAdd(&d_s[tid], t);
    }
}

// ---- K7: pooled = s@W2/N + b2 ; softmax ; write 16 floats ----
__global__ void out_kernel(const float* __restrict__ W2, const float* __restrict__ b2,
                           float* __restrict__ out)
{
    int k = threadIdx.x;
    float p = -INFINITY;
    if (k < HIDDEN) {
        float acc = 0.f;
#pragma unroll
        for (int j = 0; j < HIDDEN; j++) acc += d_s[j] * W2[j * HIDDEN + k];
        p = acc * (1.0f / (float)N_NODES) + b2[k];
    }
    float m = p;
#pragma unroll
    for (int off = 16; off > 0; off >>= 1)
        m = fmaxf(m, __shfl_xor_sync(0xffffffffu, m, off));
    float e = (k < HIDDEN) ? expf(p - m) : 0.f;
    float ssum = e;
#pragma unroll
    for (int off = 16; off > 0; off >>= 1)
        ssum += __shfl_xor_sync(0xffffffffu, ssum, off);
    if (k < HIDDEN) out[k] = e / ssum;
}

extern "C" void kernel_launch(void* const* d_in, const int* in_sizes, int n_in,
                              void* d_out, int out_size)
{
    const float* x  = (const float*)d_in[0];
    const int*   ei = (const int*)d_in[1];     // [2, E] row-major
    const float* W1 = (const float*)d_in[2];
    const float* b1 = (const float*)d_in[3];
    const float* W2 = (const float*)d_in[4];
    const float* b2 = (const float*)d_in[5];
    const int* src = ei;
    const int* dst = ei + N_EDGES;
    float* out = (float*)d_out;

    cudaFuncSetAttribute(gemm_kernel, cudaFuncAttributeMaxDynamicSharedMemorySize,
                         2 * 8192 * sizeof(unsigned));

    // fork/join side stream for the GEMM (host-side handles only; no device mem)
    cudaStream_t s2;
    cudaStreamCreateWithFlags(&s2, cudaStreamNonBlocking);
    cudaEvent_t evFork, evJoin;
    cudaEventCreateWithFlags(&evFork, cudaEventDisableTiming);
    cudaEventCreateWithFlags(&evJoin, cudaEventDisableTiming);

    // main stream: edge pipeline
    zero_kernel<<<(N_NODES + 255) / 256, 256>>>();
    hist_kernel<<<((N_EDGES / 4) + 255) / 256, 256>>>((const int4*)dst);
    scan1_kernel<<<SCAN_BLOCKS, 1024>>>();
    cudaEventRecord(evFork, 0);                       // dinv ready

    // side stream: GEMM (reads x, W1, dinv; writes d_g)
    cudaStreamWaitEvent(s2, evFork, 0);
    gemm_kernel<<<(N_NODES + 255) / 256, 256, 2 * 8192 * sizeof(unsigned), s2>>>(x, W1);
    cudaEventRecord(evJoin, s2);

    // main stream continues: CSR build
    scan23_kernel<<<SCAN_BLOCKS, 1024>>>();
    fill_kernel<<<((N_EDGES / 4) + 255) / 256, 256>>>((const int4*)src, (const int4*)dst);

    // join: aggregation needs d_g
    cudaStreamWaitEvent(0, evJoin, 0);
    aggfin_kernel<<<(N_NODES + 63) / 64, 256>>>(b1);
    out_kernel<<<1, 32>>>(W2, b2, out);
}